// round 2
// baseline (speedup 1.0000x reference)
#include <cuda_runtime.h>
#include <math.h>
#include <stdint.h>

// Problem constants (fixed by setup_inputs)
#define B_   2
#define S_   2048
#define D_   2048
#define H_   16
#define HD_  128
#define QKVN (3 * D_)      // 6144
#define M_   (B_ * S_)     // 4096

// Scratch (allocation-free contract: __device__ globals)
__device__ float g_qkv[(size_t)M_ * QKVN];  // [B,S,H,3*hd] packed = [4096, 6144]
__device__ float g_ctx[(size_t)M_ * D_];    // [B,S,D]

// ---------------------------------------------------------------------------
// SGEMM (NT): C[m,n] = sum_k A[m,k] * Bm[n,k] + bias[n]
// Both A and Bm are row-major with K contiguous. 128x128 tile, BK=8,
// 256 threads, 8x8 per thread. Requires M%128==0, N%128==0, K%8==0.
// ---------------------------------------------------------------------------
__global__ void __launch_bounds__(256) sgemm_nt_bias(
    const float* __restrict__ A, const float* __restrict__ Bm,
    const float* __restrict__ bias, float* __restrict__ C,
    int M, int N, int K)
{
    __shared__ float As[8][128];
    __shared__ float Bs[8][128];

    const int tid = threadIdx.x;
    const int tx = tid & 15;
    const int ty = tid >> 4;
    const int mBase = blockIdx.y * 128;
    const int nBase = blockIdx.x * 128;

    float acc[8][8];
#pragma unroll
    for (int i = 0; i < 8; i++)
#pragma unroll
        for (int j = 0; j < 8; j++) acc[i][j] = 0.f;

    const int lrow = tid >> 1;          // 0..127
    const int lcol = (tid & 1) * 4;     // 0 or 4
    const float* Aptr = A + (size_t)(mBase + lrow) * K + lcol;
    const float* Bptr = Bm + (size_t)(nBase + lrow) * K + lcol;

    for (int k0 = 0; k0 < K; k0 += 8) {
        float4 av = *(const float4*)(Aptr + k0);
        float4 bv = *(const float4*)(Bptr + k0);
        __syncthreads();
        As[lcol + 0][lrow] = av.x; As[lcol + 1][lrow] = av.y;
        As[lcol + 2][lrow] = av.z; As[lcol + 3][lrow] = av.w;
        Bs[lcol + 0][lrow] = bv.x; Bs[lcol + 1][lrow] = bv.y;
        Bs[lcol + 2][lrow] = bv.z; Bs[lcol + 3][lrow] = bv.w;
        __syncthreads();
#pragma unroll
        for (int kk = 0; kk < 8; kk++) {
            float a[8], bb[8];
            *(float4*)(a)      = *(const float4*)(&As[kk][ty * 8]);
            *(float4*)(a + 4)  = *(const float4*)(&As[kk][ty * 8 + 4]);
            *(float4*)(bb)     = *(const float4*)(&Bs[kk][tx * 8]);
            *(float4*)(bb + 4) = *(const float4*)(&Bs[kk][tx * 8 + 4]);
#pragma unroll
            for (int i = 0; i < 8; i++)
#pragma unroll
                for (int j = 0; j < 8; j++)
                    acc[i][j] += a[i] * bb[j];
        }
    }

#pragma unroll
    for (int i = 0; i < 8; i++) {
        float* crow = C + (size_t)(mBase + ty * 8 + i) * N + nBase + tx * 8;
        float4 o0, o1;
        o0.x = acc[i][0] + bias[nBase + tx * 8 + 0];
        o0.y = acc[i][1] + bias[nBase + tx * 8 + 1];
        o0.z = acc[i][2] + bias[nBase + tx * 8 + 2];
        o0.w = acc[i][3] + bias[nBase + tx * 8 + 3];
        o1.x = acc[i][4] + bias[nBase + tx * 8 + 4];
        o1.y = acc[i][5] + bias[nBase + tx * 8 + 5];
        o1.z = acc[i][6] + bias[nBase + tx * 8 + 6];
        o1.w = acc[i][7] + bias[nBase + tx * 8 + 7];
        *(float4*)(crow)     = o0;
        *(float4*)(crow + 4) = o1;
    }
}

// ---------------------------------------------------------------------------
// RoPE in-place on q and k first ROT_DIMS(=32) dims of every head.
// qkv layout per row: [H=16][q(128) | k(128) | v(128)]
// one thread per (b*s, h, i<16) rotation pair
// ---------------------------------------------------------------------------
__global__ void rope_kernel(float* __restrict__ qkv)
{
    int idx = blockIdx.x * blockDim.x + threadIdx.x;
    if (idx >= B_ * S_ * H_ * 16) return;
    int i  = idx & 15;
    int h  = (idx >> 4) & (H_ - 1);
    int bs = idx >> 8;           // 0..B*S-1
    int s  = bs & (S_ - 1);

    // inv_freq[i] = 10000^{-(2i)/32} = 10000^{-i/16}; double pow for accuracy
    float freq = (float)pow(10000.0, -(double)i / 16.0);
    float ang  = (float)s * freq;
    float sn, c;
    sincosf(ang, &sn, &c);

    float* p = qkv + ((size_t)bs * H_ + h) * 384;
    float q1 = p[i], q2 = p[i + 16];
    p[i]      = q1 * c - q2 * sn;
    p[i + 16] = q2 * c + q1 * sn;

    float* pk = p + 128;
    float k1 = pk[i], k2 = pk[i + 16];
    pk[i]      = k1 * c - k2 * sn;
    pk[i + 16] = k2 * c + k1 * sn;
}

// ---------------------------------------------------------------------------
// Flash attention (causal), fp32. One block = one (b,h, 64-row q-tile).
// BM=BN=64, hd=128, 256 threads. Online softmax; O accumulator in registers.
// ---------------------------------------------------------------------------
#define QSTR 132   // padded row stride for Q/K/V smem tiles
#define PSTR 65    // padded row stride for P tile
#define FLASH_SMEM ((3 * 64 * QSTR + 64 * PSTR + 3 * 64) * 4)  // 118784 B

__global__ void __launch_bounds__(256) flash_kernel(
    const float* __restrict__ qkv, float* __restrict__ ctx)
{
    extern __shared__ float sm[];
    float* Qs    = sm;                    // [64][QSTR]
    float* Ks    = Qs + 64 * QSTR;
    float* Vs    = Ks + 64 * QSTR;
    float* Ps    = Vs + 64 * QSTR;        // [64][PSTR]
    float* mrow  = Ps + 64 * PSTR;        // [64]
    float* lrowS = mrow + 64;             // [64]
    float* arowS = lrowS + 64;            // [64]

    const int tid = threadIdx.x;
    const int qt  = blockIdx.x;           // q tile (0..31)
    const int bh  = blockIdx.y;           // 0..31
    const int b   = bh >> 4;
    const int h   = bh & 15;
    const float scale = 0.088388347648318447f;   // 1/sqrt(128)

    const float* base = qkv + (size_t)b * S_ * (H_ * 384) + (size_t)h * 384;
    const int q0 = qt * 64;

    // Load + pre-scale Q tile
    for (int i = tid; i < 64 * 32; i += 256) {
        int r  = i >> 5;
        int d4 = (i & 31) << 2;
        float4 v = *(const float4*)(base + (size_t)(q0 + r) * (H_ * 384) + d4);
        float* dst = Qs + r * QSTR + d4;
        dst[0] = v.x * scale; dst[1] = v.y * scale;
        dst[2] = v.z * scale; dst[3] = v.w * scale;
    }
    if (tid < 64) { mrow[tid] = -1e30f; lrowS[tid] = 0.f; }

    float O[4][8];
#pragma unroll
    for (int i = 0; i < 4; i++)
#pragma unroll
        for (int j = 0; j < 8; j++) O[i][j] = 0.f;

    const int ty = tid >> 4, tx = tid & 15;
    const int r0 = ty * 4;

    for (int jt = 0; jt <= qt; jt++) {
        const int k0 = jt * 64;
        // Load K,V tiles (prev iteration's consumers finished at loop-end sync)
        for (int i = tid; i < 64 * 32; i += 256) {
            int r  = i >> 5;
            int d4 = (i & 31) << 2;
            const float* kp = base + (size_t)(k0 + r) * (H_ * 384) + 128 + d4;
            float4 kv = *(const float4*)(kp);
            float4 vv = *(const float4*)(kp + 128);
            float* kd = Ks + r * QSTR + d4;
            kd[0] = kv.x; kd[1] = kv.y; kd[2] = kv.z; kd[3] = kv.w;
            float* vd = Vs + r * QSTR + d4;
            vd[0] = vv.x; vd[1] = vv.y; vd[2] = vv.z; vd[3] = vv.w;
        }
        __syncthreads();

        // S = Q K^T  (4x4 per thread; cols interleaved: c = tx + 16*j)
        float s4[4][4];
#pragma unroll
        for (int i = 0; i < 4; i++)
#pragma unroll
            for (int j = 0; j < 4; j++) s4[i][j] = 0.f;

#pragma unroll 8
        for (int d = 0; d < 128; d += 4) {
            float4 qa[4], ka[4];
#pragma unroll
            for (int i = 0; i < 4; i++)
                qa[i] = *(const float4*)(Qs + (r0 + i) * QSTR + d);
#pragma unroll
            for (int j = 0; j < 4; j++)
                ka[j] = *(const float4*)(Ks + (tx + 16 * j) * QSTR + d);
#pragma unroll
            for (int i = 0; i < 4; i++)
#pragma unroll
                for (int j = 0; j < 4; j++)
                    s4[i][j] += qa[i].x * ka[j].x + qa[i].y * ka[j].y
                              + qa[i].z * ka[j].z + qa[i].w * ka[j].w;
        }

        const bool diag = (jt == qt);
#pragma unroll
        for (int i = 0; i < 4; i++) {
            int gr = q0 + r0 + i;
#pragma unroll
            for (int j = 0; j < 4; j++) {
                int c  = tx + 16 * j;
                int gc = k0 + c;
                Ps[(r0 + i) * PSTR + c] = (diag && gc > gr) ? -1e30f : s4[i][j];
            }
        }
        __syncthreads();

        // Online softmax: 4 threads per row
        {
            int r    = tid >> 2;
            int part = tid & 3;
            float* prow = Ps + r * PSTR + part * 16;
            float lm = -1e30f;
#pragma unroll
            for (int c = 0; c < 16; c++) lm = fmaxf(lm, prow[c]);
            lm = fmaxf(lm, __shfl_xor_sync(0xffffffffu, lm, 1));
            lm = fmaxf(lm, __shfl_xor_sync(0xffffffffu, lm, 2));
            float mold = mrow[r];
            float mnew = fmaxf(mold, lm);
            float lsum = 0.f;
#pragma unroll
            for (int c = 0; c < 16; c++) {
                float e = __expf(prow[c] - mnew);
                prow[c] = e;
                lsum += e;
            }
            lsum += __shfl_xor_sync(0xffffffffu, lsum, 1);
            lsum += __shfl_xor_sync(0xffffffffu, lsum, 2);
            if (part == 0) {
                float al = __expf(mold - mnew);
                arowS[r] = al;
                lrowS[r] = lrowS[r] * al + lsum;
                mrow[r]  = mnew;
            }
        }
        __syncthreads();

        // O = O*alpha + P @ V   (cols: tx*8 .. tx*8+7)
        const int oc = tx * 8;
#pragma unroll
        for (int i = 0; i < 4; i++) {
            float al = arowS[r0 + i];
#pragma unroll
            for (int j = 0; j < 8; j++) O[i][j] *= al;
        }
        for (int kk = 0; kk < 64; kk++) {
            float4 v0 = *(const float4*)(Vs + kk * QSTR + oc);
            float4 v1 = *(const float4*)(Vs + kk * QSTR + oc + 4);
#pragma unroll
            for (int i = 0; i < 4; i++) {
                float p = Ps[(r0 + i) * PSTR + kk];
                O[i][0] += p * v0.x; O[i][1] += p * v0.y;
                O[i][2] += p * v0.z; O[i][3] += p * v0.w;
                O[i][4] += p * v1.x; O[i][5] += p * v1.y;
                O[i][6] += p * v1.z; O[i][7] += p * v1.w;
            }
        }
        __syncthreads();
    }

    // Normalize and write ctx[b, s, h*128 + c]
    const int oc = tx * 8;
#pragma unroll
    for (int i = 0; i < 4; i++) {
        float inv = 1.0f / lrowS[r0 + i];
        int gs = q0 + r0 + i;
        float* dst = ctx + (size_t)(b * S_ + gs) * D_ + h * HD_ + oc;
        float4 o0, o1;
        o0.x = O[i][0] * inv; o0.y = O[i][1] * inv;
        o0.z = O[i][2] * inv; o0.w = O[i][3] * inv;
        o1.x = O[i][4] * inv; o1.y = O[i][5] * inv;
        o1.z = O[i][6] * inv; o1.w = O[i][7] * inv;
        *(float4*)(dst)     = o0;
        *(float4*)(dst + 4) = o1;
    }
}

// ---------------------------------------------------------------------------
// kernel_launch
// inputs (metadata order): x, W_qkv, b_qkv, W_out, b_out
// ---------------------------------------------------------------------------
extern "C" void kernel_launch(void* const* d_in, const int* in_sizes, int n_in,
                              void* d_out, int out_size)
{
    const float* x     = (const float*)d_in[0];
    const float* W_qkv = (const float*)d_in[1];
    const float* b_qkv = (const float*)d_in[2];
    const float* W_out = (const float*)d_in[3];
    const float* b_out = (const float*)d_in[4];
    float* out = (float*)d_out;

    float *qkv = nullptr, *ctx = nullptr;
    cudaGetSymbolAddress((void**)&qkv, g_qkv);
    cudaGetSymbolAddress((void**)&ctx, g_ctx);

    cudaFuncSetAttribute(flash_kernel,
                         cudaFuncAttributeMaxDynamicSharedMemorySize,
                         FLASH_SMEM);

    dim3 blk(256);
    // 1) QKV projection: [4096,2048] @ [6144,2048]^T -> [4096,6144]
    sgemm_nt_bias<<<dim3(QKVN / 128, M_ / 128), blk>>>(x, W_qkv, b_qkv, qkv,
                                                       M_, QKVN, D_);
    // 2) RoPE in-place on q,k
    rope_kernel<<<(B_ * S_ * H_ * 16) / 256, 256>>>(qkv);
    // 3) causal flash attention -> ctx [4096, 2048]
    flash_kernel<<<dim3(S_ / 64, B_ * H_), blk, FLASH_SMEM>>>(qkv, ctx);
    // 4) output projection: ctx @ W_out^T + b_out -> out
    sgemm_nt_bias<<<dim3(D_ / 128, M_ / 128), blk>>>(ctx, W_out, b_out, out,
                                                     M_, D_, D_);
}

// round 3
// speedup vs baseline: 1.8888x; 1.8888x over previous
#include <cuda_runtime.h>
#include <math.h>
#include <stdint.h>

// Problem constants (fixed by setup_inputs)
#define B_   2
#define S_   2048
#define D_   2048
#define H_   16
#define HD_  128
#define QKVN (3 * D_)      // 6144
#define M_   (B_ * S_)     // 4096

// Scratch (allocation-free contract: __device__ globals)
__device__ float g_qkv[(size_t)M_ * QKVN];  // [B,S,H,3*hd] packed = [4096, 6144]
__device__ float g_ctx[(size_t)M_ * D_];    // [B,S,D]

// ---------------------------------------------------------------------------
// TF32 tensor-core GEMM (NT): C[m,n] = sum_k A[m,k]*Bm[n,k] + bias[n]
// A: [M,K] row-major, Bm: [N,K] row-major (both K-contiguous).
// Block tile 128x128, BK=32, 256 threads (8 warps), warp tile 64x32.
// mma.sync.aligned.m16n8k8.row.col.f32.tf32.tf32.f32, fp32 accum.
// Smem m-major, row stride 36 floats: coalesced gmem, conflict-free STS.128
// and conflict-free fragment LDS.32. Double-buffered.
// ---------------------------------------------------------------------------
#define GSTR 36
#define OPSZ (128 * GSTR)                  // floats per operand buffer
#define GEMM_SMEM (4 * OPSZ * 4)           // 73728 bytes

__device__ __forceinline__ uint32_t f2tf32(float f) {
    uint32_t u;
    asm("cvt.rna.tf32.f32 %0, %1;" : "=r"(u) : "f"(f));
    return u;
}

__device__ __forceinline__ void mma_tf32(
    float& d0, float& d1, float& d2, float& d3,
    uint32_t a0, uint32_t a1, uint32_t a2, uint32_t a3,
    uint32_t b0, uint32_t b1)
{
    asm volatile(
        "mma.sync.aligned.m16n8k8.row.col.f32.tf32.tf32.f32 "
        "{%0,%1,%2,%3}, {%4,%5,%6,%7}, {%8,%9}, {%0,%1,%2,%3};"
        : "+f"(d0), "+f"(d1), "+f"(d2), "+f"(d3)
        : "r"(a0), "r"(a1), "r"(a2), "r"(a3), "r"(b0), "r"(b1));
}

__global__ void __launch_bounds__(256) tf32_gemm_nt_bias(
    const float* __restrict__ A, const float* __restrict__ Bm,
    const float* __restrict__ bias, float* __restrict__ C,
    int M, int N, int K)
{
    extern __shared__ float sg[];
    // layout: [buf0: As | Bs][buf1: As | Bs]
    const int tid  = threadIdx.x;
    const int lane = tid & 31;
    const int warp = tid >> 5;
    const int r = lane >> 2;        // groupID
    const int t = lane & 3;         // threadID_in_group
    const int wm = (warp >> 2) * 64;
    const int wn = (warp & 3) * 32;
    const int mBase = blockIdx.y * 128;
    const int nBase = blockIdx.x * 128;

    float acc[4][4][4];
#pragma unroll
    for (int i = 0; i < 4; i++)
#pragma unroll
        for (int j = 0; j < 4; j++)
#pragma unroll
            for (int q = 0; q < 4; q++) acc[i][j][q] = 0.f;

    // gmem->smem mapping: chunk c = tid + 256*i (i<4); m = c>>3, kc = (c&7)*4
    const int lm  = tid >> 3;            // rows handled: lm, lm+32, lm+64, lm+96
    const int lkc = (tid & 7) * 4;

    const float* Ag = A  + (size_t)(mBase + lm) * K + lkc;
    const float* Bg = Bm + (size_t)(nBase + lm) * K + lkc;

    const int nt = K / 32;
    float4 va[4], vb[4];

    // prologue: load tile 0
#pragma unroll
    for (int i = 0; i < 4; i++) {
        va[i] = *(const float4*)(Ag + (size_t)(32 * i) * K);
        vb[i] = *(const float4*)(Bg + (size_t)(32 * i) * K);
    }
    {
        float* As = sg;
        float* Bs = sg + OPSZ;
#pragma unroll
        for (int i = 0; i < 4; i++) {
            float4 ta, tb;
            ta.x = __uint_as_float(f2tf32(va[i].x));
            ta.y = __uint_as_float(f2tf32(va[i].y));
            ta.z = __uint_as_float(f2tf32(va[i].z));
            ta.w = __uint_as_float(f2tf32(va[i].w));
            tb.x = __uint_as_float(f2tf32(vb[i].x));
            tb.y = __uint_as_float(f2tf32(vb[i].y));
            tb.z = __uint_as_float(f2tf32(vb[i].z));
            tb.w = __uint_as_float(f2tf32(vb[i].w));
            *(float4*)(As + (lm + 32 * i) * GSTR + lkc) = ta;
            *(float4*)(Bs + (lm + 32 * i) * GSTR + lkc) = tb;
        }
    }
    __syncthreads();

    int p = 0;
    for (int kt = 0; kt < nt; kt++) {
        // prefetch next tile into regs
        if (kt + 1 < nt) {
            const float* Agn = Ag + (size_t)(kt + 1) * 32;
            const float* Bgn = Bg + (size_t)(kt + 1) * 32;
#pragma unroll
            for (int i = 0; i < 4; i++) {
                va[i] = *(const float4*)(Agn + (size_t)(32 * i) * K);
                vb[i] = *(const float4*)(Bgn + (size_t)(32 * i) * K);
            }
        }

        const float* As = sg + p * 2 * OPSZ;
        const float* Bs = As + OPSZ;

#pragma unroll
        for (int s = 0; s < 4; s++) {
            const int kb = s * 8;
            uint32_t af[4][4];
#pragma unroll
            for (int i = 0; i < 4; i++) {
                const float* a0p = As + (wm + i * 16 + r) * GSTR + kb + t;
                const float* a1p = a0p + 8 * GSTR;
                af[i][0] = __float_as_uint(a0p[0]);
                af[i][1] = __float_as_uint(a1p[0]);
                af[i][2] = __float_as_uint(a0p[4]);
                af[i][3] = __float_as_uint(a1p[4]);
            }
            uint32_t bf[4][2];
#pragma unroll
            for (int j = 0; j < 4; j++) {
                const float* b0p = Bs + (wn + j * 8 + r) * GSTR + kb + t;
                bf[j][0] = __float_as_uint(b0p[0]);
                bf[j][1] = __float_as_uint(b0p[4]);
            }
#pragma unroll
            for (int i = 0; i < 4; i++)
#pragma unroll
                for (int j = 0; j < 4; j++)
                    mma_tf32(acc[i][j][0], acc[i][j][1], acc[i][j][2], acc[i][j][3],
                             af[i][0], af[i][1], af[i][2], af[i][3],
                             bf[j][0], bf[j][1]);
        }

        if (kt + 1 < nt) {
            float* Asn = sg + (p ^ 1) * 2 * OPSZ;
            float* Bsn = Asn + OPSZ;
#pragma unroll
            for (int i = 0; i < 4; i++) {
                float4 ta, tb;
                ta.x = __uint_as_float(f2tf32(va[i].x));
                ta.y = __uint_as_float(f2tf32(va[i].y));
                ta.z = __uint_as_float(f2tf32(va[i].z));
                ta.w = __uint_as_float(f2tf32(va[i].w));
                tb.x = __uint_as_float(f2tf32(vb[i].x));
                tb.y = __uint_as_float(f2tf32(vb[i].y));
                tb.z = __uint_as_float(f2tf32(vb[i].z));
                tb.w = __uint_as_float(f2tf32(vb[i].w));
                *(float4*)(Asn + (lm + 32 * i) * GSTR + lkc) = ta;
                *(float4*)(Bsn + (lm + 32 * i) * GSTR + lkc) = tb;
            }
            __syncthreads();
            p ^= 1;
        }
    }

    // epilogue: D fragment c0:(r, 2t) c1:(r, 2t+1) c2:(r+8, 2t) c3:(r+8, 2t+1)
#pragma unroll
    for (int i = 0; i < 4; i++) {
        const int row0 = mBase + wm + i * 16 + r;
#pragma unroll
        for (int j = 0; j < 4; j++) {
            const int col = nBase + wn + j * 8 + 2 * t;
            const float bz0 = bias[col], bz1 = bias[col + 1];
            float2 u0, u1;
            u0.x = acc[i][j][0] + bz0;
            u0.y = acc[i][j][1] + bz1;
            u1.x = acc[i][j][2] + bz0;
            u1.y = acc[i][j][3] + bz1;
            *(float2*)(C + (size_t)row0 * N + col)       = u0;
            *(float2*)(C + (size_t)(row0 + 8) * N + col) = u1;
        }
    }
}

// ---------------------------------------------------------------------------
// RoPE in-place on q and k first ROT_DIMS(=32) dims of every head.
// ---------------------------------------------------------------------------
__global__ void rope_kernel(float* __restrict__ qkv)
{
    int idx = blockIdx.x * blockDim.x + threadIdx.x;
    if (idx >= B_ * S_ * H_ * 16) return;
    int i  = idx & 15;
    int h  = (idx >> 4) & (H_ - 1);
    int bs = idx >> 8;
    int s  = bs & (S_ - 1);

    float freq = (float)pow(10000.0, -(double)i / 16.0);
    float ang  = (float)s * freq;
    float sn, c;
    sincosf(ang, &sn, &c);

    float* p = qkv + ((size_t)bs * H_ + h) * 384;
    float q1 = p[i], q2 = p[i + 16];
    p[i]      = q1 * c - q2 * sn;
    p[i + 16] = q2 * c + q1 * sn;

    float* pk = p + 128;
    float k1 = pk[i], k2 = pk[i + 16];
    pk[i]      = k1 * c - k2 * sn;
    pk[i + 16] = k2 * c + k1 * sn;
}

// ---------------------------------------------------------------------------
// Flash attention (causal), fp32 (unchanged from R2 baseline).
// ---------------------------------------------------------------------------
#define QSTR 132
#define PSTR 65
#define FLASH_SMEM ((3 * 64 * QSTR + 64 * PSTR + 3 * 64) * 4)  // 118784 B

__global__ void __launch_bounds__(256) flash_kernel(
    const float* __restrict__ qkv, float* __restrict__ ctx)
{
    extern __shared__ float sm[];
    float* Qs    = sm;
    float* Ks    = Qs + 64 * QSTR;
    float* Vs    = Ks + 64 * QSTR;
    float* Ps    = Vs + 64 * QSTR;
    float* mrow  = Ps + 64 * PSTR;
    float* lrowS = mrow + 64;
    float* arowS = lrowS + 64;

    const int tid = threadIdx.x;
    const int qt  = blockIdx.x;
    const int bh  = blockIdx.y;
    const int b   = bh >> 4;
    const int h   = bh & 15;
    const float scale = 0.088388347648318447f;

    const float* base = qkv + (size_t)b * S_ * (H_ * 384) + (size_t)h * 384;
    const int q0 = qt * 64;

    for (int i = tid; i < 64 * 32; i += 256) {
        int r  = i >> 5;
        int d4 = (i & 31) << 2;
        float4 v = *(const float4*)(base + (size_t)(q0 + r) * (H_ * 384) + d4);
        float* dst = Qs + r * QSTR + d4;
        dst[0] = v.x * scale; dst[1] = v.y * scale;
        dst[2] = v.z * scale; dst[3] = v.w * scale;
    }
    if (tid < 64) { mrow[tid] = -1e30f; lrowS[tid] = 0.f; }

    float O[4][8];
#pragma unroll
    for (int i = 0; i < 4; i++)
#pragma unroll
        for (int j = 0; j < 8; j++) O[i][j] = 0.f;

    const int ty = tid >> 4, tx = tid & 15;
    const int r0 = ty * 4;

    for (int jt = 0; jt <= qt; jt++) {
        const int k0 = jt * 64;
        for (int i = tid; i < 64 * 32; i += 256) {
            int r  = i >> 5;
            int d4 = (i & 31) << 2;
            const float* kp = base + (size_t)(k0 + r) * (H_ * 384) + 128 + d4;
            float4 kv = *(const float4*)(kp);
            float4 vv = *(const float4*)(kp + 128);
            float* kd = Ks + r * QSTR + d4;
            kd[0] = kv.x; kd[1] = kv.y; kd[2] = kv.z; kd[3] = kv.w;
            float* vd = Vs + r * QSTR + d4;
            vd[0] = vv.x; vd[1] = vv.y; vd[2] = vv.z; vd[3] = vv.w;
        }
        __syncthreads();

        float s4[4][4];
#pragma unroll
        for (int i = 0; i < 4; i++)
#pragma unroll
            for (int j = 0; j < 4; j++) s4[i][j] = 0.f;

#pragma unroll 8
        for (int d = 0; d < 128; d += 4) {
            float4 qa[4], ka[4];
#pragma unroll
            for (int i = 0; i < 4; i++)
                qa[i] = *(const float4*)(Qs + (r0 + i) * QSTR + d);
#pragma unroll
            for (int j = 0; j < 4; j++)
                ka[j] = *(const float4*)(Ks + (tx + 16 * j) * QSTR + d);
#pragma unroll
            for (int i = 0; i < 4; i++)
#pragma unroll
                for (int j = 0; j < 4; j++)
                    s4[i][j] += qa[i].x * ka[j].x + qa[i].y * ka[j].y
                              + qa[i].z * ka[j].z + qa[i].w * ka[j].w;
        }

        const bool diag = (jt == qt);
#pragma unroll
        for (int i = 0; i < 4; i++) {
            int gr = q0 + r0 + i;
#pragma unroll
            for (int j = 0; j < 4; j++) {
                int c  = tx + 16 * j;
                int gc = k0 + c;
                Ps[(r0 + i) * PSTR + c] = (diag && gc > gr) ? -1e30f : s4[i][j];
            }
        }
        __syncthreads();

        {
            int r    = tid >> 2;
            int part = tid & 3;
            float* prow = Ps + r * PSTR + part * 16;
            float lm = -1e30f;
#pragma unroll
            for (int c = 0; c < 16; c++) lm = fmaxf(lm, prow[c]);
            lm = fmaxf(lm, __shfl_xor_sync(0xffffffffu, lm, 1));
            lm = fmaxf(lm, __shfl_xor_sync(0xffffffffu, lm, 2));
            float mold = mrow[r];
            float mnew = fmaxf(mold, lm);
            float lsum = 0.f;
#pragma unroll
            for (int c = 0; c < 16; c++) {
                float e = __expf(prow[c] - mnew);
                prow[c] = e;
                lsum += e;
            }
            lsum += __shfl_xor_sync(0xffffffffu, lsum, 1);
            lsum += __shfl_xor_sync(0xffffffffu, lsum, 2);
            if (part == 0) {
                float al = __expf(mold - mnew);
                arowS[r] = al;
                lrowS[r] = lrowS[r] * al + lsum;
                mrow[r]  = mnew;
            }
        }
        __syncthreads();

        const int oc = tx * 8;
#pragma unroll
        for (int i = 0; i < 4; i++) {
            float al = arowS[r0 + i];
#pragma unroll
            for (int j = 0; j < 8; j++) O[i][j] *= al;
        }
        for (int kk = 0; kk < 64; kk++) {
            float4 v0 = *(const float4*)(Vs + kk * QSTR + oc);
            float4 v1 = *(const float4*)(Vs + kk * QSTR + oc + 4);
#pragma unroll
            for (int i = 0; i < 4; i++) {
                float p = Ps[(r0 + i) * PSTR + kk];
                O[i][0] += p * v0.x; O[i][1] += p * v0.y;
                O[i][2] += p * v0.z; O[i][3] += p * v0.w;
                O[i][4] += p * v1.x; O[i][5] += p * v1.y;
                O[i][6] += p * v1.z; O[i][7] += p * v1.w;
            }
        }
        __syncthreads();
    }

    const int oc = tx * 8;
#pragma unroll
    for (int i = 0; i < 4; i++) {
        float inv = 1.0f / lrowS[r0 + i];
        int gs = q0 + r0 + i;
        float* dst = ctx + (size_t)(b * S_ + gs) * D_ + h * HD_ + oc;
        float4 o0, o1;
        o0.x = O[i][0] * inv; o0.y = O[i][1] * inv;
        o0.z = O[i][2] * inv; o0.w = O[i][3] * inv;
        o1.x = O[i][4] * inv; o1.y = O[i][5] * inv;
        o1.z = O[i][6] * inv; o1.w = O[i][7] * inv;
        *(float4*)(dst)     = o0;
        *(float4*)(dst + 4) = o1;
    }
}

// ---------------------------------------------------------------------------
// kernel_launch
// inputs (metadata order): x, W_qkv, b_qkv, W_out, b_out
// ---------------------------------------------------------------------------
extern "C" void kernel_launch(void* const* d_in, const int* in_sizes, int n_in,
                              void* d_out, int out_size)
{
    const float* x     = (const float*)d_in[0];
    const float* W_qkv = (const float*)d_in[1];
    const float* b_qkv = (const float*)d_in[2];
    const float* W_out = (const float*)d_in[3];
    const float* b_out = (const float*)d_in[4];
    float* out = (float*)d_out;

    float *qkv = nullptr, *ctx = nullptr;
    cudaGetSymbolAddress((void**)&qkv, g_qkv);
    cudaGetSymbolAddress((void**)&ctx, g_ctx);

    cudaFuncSetAttribute(tf32_gemm_nt_bias,
                         cudaFuncAttributeMaxDynamicSharedMemorySize,
                         GEMM_SMEM);
    cudaFuncSetAttribute(flash_kernel,
                         cudaFuncAttributeMaxDynamicSharedMemorySize,
                         FLASH_SMEM);

    dim3 blk(256);
    // 1) QKV projection: [4096,2048] @ [6144,2048]^T -> [4096,6144]
    tf32_gemm_nt_bias<<<dim3(QKVN / 128, M_ / 128), blk, GEMM_SMEM>>>(
        x, W_qkv, b_qkv, qkv, M_, QKVN, D_);
    // 2) RoPE in-place on q,k
    rope_kernel<<<(B_ * S_ * H_ * 16) / 256, 256>>>(qkv);
    // 3) causal flash attention -> ctx [4096, 2048]
    flash_kernel<<<dim3(S_ / 64, B_ * H_), blk, FLASH_SMEM>>>(qkv, ctx);
    // 4) output projection: ctx @ W_out^T + b_out -> out
    tf32_gemm_nt_bias<<<dim3(D_ / 128, M_ / 128), blk, GEMM_SMEM>>>(
        ctx, W_out, b_out, out, M_, D_, D_);
}

// round 4
// speedup vs baseline: 1.9524x; 1.0336x over previous
#include <cuda_runtime.h>
#include <math.h>
#include <stdint.h>

// Problem constants (fixed by setup_inputs)
#define B_   2
#define S_   2048
#define D_   2048
#define H_   16
#define HD_  128
#define QKVN (3 * D_)      // 6144
#define M_   (B_ * S_)     // 4096

// Scratch (allocation-free contract: __device__ globals)
__device__ float g_qkv[(size_t)M_ * QKVN];  // [B,S,H, q|k|v (384)]
__device__ float g_ctx[(size_t)M_ * D_];    // [B,S,D]
// Pre-split tf32 hi/lo planes, layout [B*H][S][128]
#define PLN ((size_t)B_ * H_ * S_ * HD_)
__device__ float g_qhi[PLN];
__device__ float g_qlo[PLN];
__device__ float g_khi[PLN];
__device__ float g_klo[PLN];
__device__ float g_vhi[PLN];
__device__ float g_vlo[PLN];

__device__ __forceinline__ uint32_t f2tf32(float f) {
    uint32_t u;
    asm("cvt.rna.tf32.f32 %0, %1;" : "=r"(u) : "f"(f));
    return u;
}

__device__ __forceinline__ void mma_tf32(
    float& d0, float& d1, float& d2, float& d3,
    uint32_t a0, uint32_t a1, uint32_t a2, uint32_t a3,
    uint32_t b0, uint32_t b1)
{
    asm volatile(
        "mma.sync.aligned.m16n8k8.row.col.f32.tf32.tf32.f32 "
        "{%0,%1,%2,%3}, {%4,%5,%6,%7}, {%8,%9}, {%0,%1,%2,%3};"
        : "+f"(d0), "+f"(d1), "+f"(d2), "+f"(d3)
        : "r"(a0), "r"(a1), "r"(a2), "r"(a3), "r"(b0), "r"(b1));
}

// exp(x) for x <= 0, FMA-pipe only, rel err ~2e-6, exact 0 below ~-87.
__device__ __forceinline__ float fast_exp(float x) {
    x = fmaxf(x, -100.0f);
    const float L2E = 1.4426950408889634f;
    float y = fmaf(x, L2E, 12582912.0f);          // round(x*log2e) via magic
    int   e = __float_as_int(y) - 0x4B400000;     // integer part n
    float n = y - 12582912.0f;
    float f = fmaf(x, L2E, -n);                   // frac in [-0.5, 0.5]
    float p = 0.00133335581f;
    p = fmaf(p, f, 0.00961812911f);
    p = fmaf(p, f, 0.05550410866f);
    p = fmaf(p, f, 0.24022650696f);
    p = fmaf(p, f, 0.69314718056f);
    p = fmaf(p, f, 1.0f);
    e = max(e, -127);
    return p * __int_as_float((e + 127) << 23);
}

// ---------------------------------------------------------------------------
// TF32 tensor-core GEMM (NT) — unchanged from R3 (passing, 332us)
// ---------------------------------------------------------------------------
#define GSTR 36
#define OPSZ (128 * GSTR)
#define GEMM_SMEM (4 * OPSZ * 4)           // 73728 bytes

__global__ void __launch_bounds__(256) tf32_gemm_nt_bias(
    const float* __restrict__ A, const float* __restrict__ Bm,
    const float* __restrict__ bias, float* __restrict__ C,
    int M, int N, int K)
{
    extern __shared__ float sg[];
    const int tid  = threadIdx.x;
    const int lane = tid & 31;
    const int warp = tid >> 5;
    const int r = lane >> 2;
    const int t = lane & 3;
    const int wm = (warp >> 2) * 64;
    const int wn = (warp & 3) * 32;
    const int mBase = blockIdx.y * 128;
    const int nBase = blockIdx.x * 128;

    float acc[4][4][4];
#pragma unroll
    for (int i = 0; i < 4; i++)
#pragma unroll
        for (int j = 0; j < 4; j++)
#pragma unroll
            for (int q = 0; q < 4; q++) acc[i][j][q] = 0.f;

    const int lm  = tid >> 3;
    const int lkc = (tid & 7) * 4;

    const float* Ag = A  + (size_t)(mBase + lm) * K + lkc;
    const float* Bg = Bm + (size_t)(nBase + lm) * K + lkc;

    const int nt = K / 32;
    float4 va[4], vb[4];

#pragma unroll
    for (int i = 0; i < 4; i++) {
        va[i] = *(const float4*)(Ag + (size_t)(32 * i) * K);
        vb[i] = *(const float4*)(Bg + (size_t)(32 * i) * K);
    }
    {
        float* As = sg;
        float* Bs = sg + OPSZ;
#pragma unroll
        for (int i = 0; i < 4; i++) {
            float4 ta, tb;
            ta.x = __uint_as_float(f2tf32(va[i].x));
            ta.y = __uint_as_float(f2tf32(va[i].y));
            ta.z = __uint_as_float(f2tf32(va[i].z));
            ta.w = __uint_as_float(f2tf32(va[i].w));
            tb.x = __uint_as_float(f2tf32(vb[i].x));
            tb.y = __uint_as_float(f2tf32(vb[i].y));
            tb.z = __uint_as_float(f2tf32(vb[i].z));
            tb.w = __uint_as_float(f2tf32(vb[i].w));
            *(float4*)(As + (lm + 32 * i) * GSTR + lkc) = ta;
            *(float4*)(Bs + (lm + 32 * i) * GSTR + lkc) = tb;
        }
    }
    __syncthreads();

    int p = 0;
    for (int kt = 0; kt < nt; kt++) {
        if (kt + 1 < nt) {
            const float* Agn = Ag + (size_t)(kt + 1) * 32;
            const float* Bgn = Bg + (size_t)(kt + 1) * 32;
#pragma unroll
            for (int i = 0; i < 4; i++) {
                va[i] = *(const float4*)(Agn + (size_t)(32 * i) * K);
                vb[i] = *(const float4*)(Bgn + (size_t)(32 * i) * K);
            }
        }

        const float* As = sg + p * 2 * OPSZ;
        const float* Bs = As + OPSZ;

#pragma unroll
        for (int s = 0; s < 4; s++) {
            const int kb = s * 8;
            uint32_t af[4][4];
#pragma unroll
            for (int i = 0; i < 4; i++) {
                const float* a0p = As + (wm + i * 16 + r) * GSTR + kb + t;
                const float* a1p = a0p + 8 * GSTR;
                af[i][0] = __float_as_uint(a0p[0]);
                af[i][1] = __float_as_uint(a1p[0]);
                af[i][2] = __float_as_uint(a0p[4]);
                af[i][3] = __float_as_uint(a1p[4]);
            }
            uint32_t bf[4][2];
#pragma unroll
            for (int j = 0; j < 4; j++) {
                const float* b0p = Bs + (wn + j * 8 + r) * GSTR + kb + t;
                bf[j][0] = __float_as_uint(b0p[0]);
                bf[j][1] = __float_as_uint(b0p[4]);
            }
#pragma unroll
            for (int i = 0; i < 4; i++)
#pragma unroll
                for (int j = 0; j < 4; j++)
                    mma_tf32(acc[i][j][0], acc[i][j][1], acc[i][j][2], acc[i][j][3],
                             af[i][0], af[i][1], af[i][2], af[i][3],
                             bf[j][0], bf[j][1]);
        }

        if (kt + 1 < nt) {
            float* Asn = sg + (p ^ 1) * 2 * OPSZ;
            float* Bsn = Asn + OPSZ;
#pragma unroll
            for (int i = 0; i < 4; i++) {
                float4 ta, tb;
                ta.x = __uint_as_float(f2tf32(va[i].x));
                ta.y = __uint_as_float(f2tf32(va[i].y));
                ta.z = __uint_as_float(f2tf32(va[i].z));
                ta.w = __uint_as_float(f2tf32(va[i].w));
                tb.x = __uint_as_float(f2tf32(vb[i].x));
                tb.y = __uint_as_float(f2tf32(vb[i].y));
                tb.z = __uint_as_float(f2tf32(vb[i].z));
                tb.w = __uint_as_float(f2tf32(vb[i].w));
                *(float4*)(Asn + (lm + 32 * i) * GSTR + lkc) = ta;
                *(float4*)(Bsn + (lm + 32 * i) * GSTR + lkc) = tb;
            }
            __syncthreads();
            p ^= 1;
        }
    }

#pragma unroll
    for (int i = 0; i < 4; i++) {
        const int row0 = mBase + wm + i * 16 + r;
#pragma unroll
        for (int j = 0; j < 4; j++) {
            const int col = nBase + wn + j * 8 + 2 * t;
            const float bz0 = bias[col], bz1 = bias[col + 1];
            float2 u0, u1;
            u0.x = acc[i][j][0] + bz0;
            u0.y = acc[i][j][1] + bz1;
            u1.x = acc[i][j][2] + bz0;
            u1.y = acc[i][j][3] + bz1;
            *(float2*)(C + (size_t)row0 * N + col)       = u0;
            *(float2*)(C + (size_t)(row0 + 8) * N + col) = u1;
        }
    }
}

// ---------------------------------------------------------------------------
// RoPE in-place on q and k (first 32 dims of every head)
// ---------------------------------------------------------------------------
__global__ void rope_kernel(float* __restrict__ qkv)
{
    int idx = blockIdx.x * blockDim.x + threadIdx.x;
    if (idx >= B_ * S_ * H_ * 16) return;
    int i  = idx & 15;
    int h  = (idx >> 4) & (H_ - 1);
    int bs = idx >> 8;
    int s  = bs & (S_ - 1);

    float freq = (float)pow(10000.0, -(double)i / 16.0);
    float ang  = (float)s * freq;
    float sn, c;
    sincosf(ang, &sn, &c);

    float* p = qkv + ((size_t)bs * H_ + h) * 384;
    float q1 = p[i], q2 = p[i + 16];
    p[i]      = q1 * c - q2 * sn;
    p[i + 16] = q2 * c + q1 * sn;

    float* pk = p + 128;
    float k1 = pk[i], k2 = pk[i + 16];
    pk[i]      = k1 * c - k2 * sn;
    pk[i + 16] = k2 * c + k1 * sn;
}

// ---------------------------------------------------------------------------
// Split pre-pass: read roped qkv, transpose to [bh][s][128], split into
// tf32 hi/lo planes. Q is pre-scaled by 1/sqrt(hd).
// ---------------------------------------------------------------------------
__device__ __forceinline__ void split4(float4 x, float* hi, float* lo, size_t off)
{
    float4 h4, l4;
    h4.x = __uint_as_float(f2tf32(x.x)); l4.x = __uint_as_float(f2tf32(x.x - h4.x));
    h4.y = __uint_as_float(f2tf32(x.y)); l4.y = __uint_as_float(f2tf32(x.y - h4.y));
    h4.z = __uint_as_float(f2tf32(x.z)); l4.z = __uint_as_float(f2tf32(x.z - h4.z));
    h4.w = __uint_as_float(f2tf32(x.w)); l4.w = __uint_as_float(f2tf32(x.w - h4.w));
    *(float4*)(hi + off) = h4;
    *(float4*)(lo + off) = l4;
}

__global__ void split_qkv_kernel(const float* __restrict__ qkv)
{
    int idx = blockIdx.x * 256 + threadIdx.x;     // B*S*H*32 total
    int d4 = (idx & 31) << 2;
    int h  = (idx >> 5) & 15;
    int bs = idx >> 9;
    int b  = bs >> 11, s = bs & 2047;

    const float* src = qkv + ((size_t)bs * H_ + h) * 384;
    size_t off = ((size_t)(b * H_ + h) * S_ + s) * HD_ + d4;

    float4 q = *(const float4*)(src + d4);
    float4 k = *(const float4*)(src + 128 + d4);
    float4 v = *(const float4*)(src + 256 + d4);
    const float sc = 0.088388347648318447f;      // 1/sqrt(128)
    q.x *= sc; q.y *= sc; q.z *= sc; q.w *= sc;

    split4(q, g_qhi, g_qlo, off);
    split4(k, g_khi, g_klo, off);
    split4(v, g_vhi, g_vlo, off);
}

// ---------------------------------------------------------------------------
// Flash attention (causal) with 3xTF32 MMA.
// Block = (qt, bh): 64 q-rows; key tiles of 32; 256 threads (8 warps).
// Warp w: S tile rows (w>>1)*16, cols (w&1)*16; O tile same rows, cols (w&1)*64.
// ---------------------------------------------------------------------------
#define KSTRF 132
#define PSTRF 36
// smem float offsets
#define SM_QHI  0
#define SM_QLO  8448
#define SM_KV   16896            // 2 bufs x 16896 (Khi|Klo|Vhi|Vlo, each 32*132)
#define SM_PHI  50688
#define SM_PLO  52992
#define SM_MR   55296
#define SM_LR   55360
#define SM_AR   55424
#define FLASH_SMEM (55488 * 4)   // 221952 bytes

__device__ __forceinline__ void cp16(uint32_t dst, const float* src)
{
    asm volatile("cp.async.cg.shared.global [%0], [%1], 16;" :: "r"(dst), "l"(src));
}

__device__ __forceinline__ void kv_issue(uint32_t sbase, int buf, size_t bh_off,
                                         int k0, int tid)
{
    const int key = tid >> 3;
    const int dq  = (tid & 7) * 16;
    const size_t src = bh_off + (size_t)(k0 + key) * HD_ + dq;
    const uint32_t drow = sbase + (uint32_t)((SM_KV + buf * 16896 + key * KSTRF + dq) * 4);
#pragma unroll
    for (int i = 0; i < 4; i++) cp16(drow + 16 * i,                 g_khi + src + 4 * i);
#pragma unroll
    for (int i = 0; i < 4; i++) cp16(drow + 4224 * 4 + 16 * i,      g_klo + src + 4 * i);
#pragma unroll
    for (int i = 0; i < 4; i++) cp16(drow + 8448 * 4 + 16 * i,      g_vhi + src + 4 * i);
#pragma unroll
    for (int i = 0; i < 4; i++) cp16(drow + 12672 * 4 + 16 * i,     g_vlo + src + 4 * i);
    asm volatile("cp.async.commit_group;" ::: "memory");
}

__global__ void __launch_bounds__(256) flash_kernel(float* __restrict__ ctx)
{
    extern __shared__ float sm[];
    uint32_t sbase;
    {
        void* gp = sm;
        sbase = (uint32_t)__cvta_generic_to_shared(gp);
    }
    const int tid  = threadIdx.x;
    const int lane = tid & 31;
    const int warp = tid >> 5;
    const int r = lane >> 2;
    const int t = lane & 3;
    const int qt = blockIdx.x;
    const int bh = blockIdx.y;           // b*16 + h
    const int q0 = qt * 64;
    const size_t bh_off = (size_t)bh * S_ * HD_;

    const int wm   = (warp >> 1) * 16;
    const int wn_s = (warp & 1) * 16;
    const int wn_o = (warp & 1) * 64;

    const int njt = 2 * qt + 2;

    // issue KV tile 0
    kv_issue(sbase, 0, bh_off, 0, tid);

    // load Q hi/lo into smem
    {
        const int qrow = tid >> 2;
        const int dq   = (tid & 3) * 32;
        const size_t src = bh_off + (size_t)(q0 + qrow) * HD_ + dq;
#pragma unroll
        for (int a = 0; a < 8; a++) {
            *(float4*)(sm + SM_QHI + qrow * KSTRF + dq + 4 * a) =
                *(const float4*)(g_qhi + src + 4 * a);
            *(float4*)(sm + SM_QLO + qrow * KSTRF + dq + 4 * a) =
                *(const float4*)(g_qlo + src + 4 * a);
        }
    }
    if (tid < 64) { sm[SM_MR + tid] = -1e30f; sm[SM_LR + tid] = 0.f; }

    float O[8][4];
#pragma unroll
    for (int j = 0; j < 8; j++)
#pragma unroll
        for (int q = 0; q < 4; q++) O[j][q] = 0.f;

    __syncthreads();

    for (int jt = 0; jt < njt; jt++) {
        const int k0  = jt * 32;
        const int buf = jt & 1;
        asm volatile("cp.async.wait_group 0;" ::: "memory");
        __syncthreads();
        if (jt + 1 < njt) kv_issue(sbase, buf ^ 1, bh_off, k0 + 32, tid);

        const float* Khi = sm + SM_KV + buf * 16896;
        const float* Klo = Khi + 4224;
        const float* Vhi = Khi + 8448;
        const float* Vlo = Khi + 12672;

        // ---- S = Q K^T (3xTF32) ----
        float sacc[2][4];
#pragma unroll
        for (int j = 0; j < 2; j++)
#pragma unroll
            for (int q = 0; q < 4; q++) sacc[j][q] = 0.f;

#pragma unroll
        for (int ks = 0; ks < 16; ks++) {
            const int kb = ks * 8;
            const float* qh = sm + SM_QHI + (wm + r) * KSTRF + kb + t;
            const float* ql = sm + SM_QLO + (wm + r) * KSTRF + kb + t;
            uint32_t ah0 = __float_as_uint(qh[0]);
            uint32_t ah1 = __float_as_uint(qh[8 * KSTRF]);
            uint32_t ah2 = __float_as_uint(qh[4]);
            uint32_t ah3 = __float_as_uint(qh[8 * KSTRF + 4]);
            uint32_t al0 = __float_as_uint(ql[0]);
            uint32_t al1 = __float_as_uint(ql[8 * KSTRF]);
            uint32_t al2 = __float_as_uint(ql[4]);
            uint32_t al3 = __float_as_uint(ql[8 * KSTRF + 4]);
#pragma unroll
            for (int j = 0; j < 2; j++) {
                const float* kh = Khi + (wn_s + 8 * j + r) * KSTRF + kb + t;
                const float* kl = Klo + (wn_s + 8 * j + r) * KSTRF + kb + t;
                uint32_t bh0 = __float_as_uint(kh[0]);
                uint32_t bh1 = __float_as_uint(kh[4]);
                uint32_t bl0 = __float_as_uint(kl[0]);
                uint32_t bl1 = __float_as_uint(kl[4]);
                mma_tf32(sacc[j][0], sacc[j][1], sacc[j][2], sacc[j][3],
                         ah0, ah1, ah2, ah3, bh0, bh1);
                mma_tf32(sacc[j][0], sacc[j][1], sacc[j][2], sacc[j][3],
                         al0, al1, al2, al3, bh0, bh1);
                mma_tf32(sacc[j][0], sacc[j][1], sacc[j][2], sacc[j][3],
                         ah0, ah1, ah2, ah3, bl0, bl1);
            }
        }

        // causal mask (only tiles overlapping diagonal)
        if (k0 + 32 > q0) {
            const int gr0 = q0 + wm + r;
            const int gr1 = gr0 + 8;
#pragma unroll
            for (int j = 0; j < 2; j++) {
                const int gc = k0 + wn_s + 8 * j + 2 * t;
                if (gc     > gr0) sacc[j][0] = -1e9f;
                if (gc + 1 > gr0) sacc[j][1] = -1e9f;
                if (gc     > gr1) sacc[j][2] = -1e9f;
                if (gc + 1 > gr1) sacc[j][3] = -1e9f;
            }
        }

        // store S (fp32) into Phi staging
#pragma unroll
        for (int j = 0; j < 2; j++) {
            float2 u0, u1;
            u0.x = sacc[j][0]; u0.y = sacc[j][1];
            u1.x = sacc[j][2]; u1.y = sacc[j][3];
            *(float2*)(sm + SM_PHI + (wm + r)     * PSTRF + wn_s + 8 * j + 2 * t) = u0;
            *(float2*)(sm + SM_PHI + (wm + r + 8) * PSTRF + wn_s + 8 * j + 2 * t) = u1;
        }
        __syncthreads();

        // ---- online softmax: 4 threads per row, 8 cols each ----
        {
            const int row  = tid >> 2;
            const int part = tid & 3;
            float* prow = sm + SM_PHI + row * PSTRF + part * 8;
            float4 x0 = *(float4*)(prow);
            float4 x1 = *(float4*)(prow + 4);
            float lm = fmaxf(fmaxf(fmaxf(x0.x, x0.y), fmaxf(x0.z, x0.w)),
                             fmaxf(fmaxf(x1.x, x1.y), fmaxf(x1.z, x1.w)));
            lm = fmaxf(lm, __shfl_xor_sync(0xffffffffu, lm, 1));
            lm = fmaxf(lm, __shfl_xor_sync(0xffffffffu, lm, 2));
            float mold = sm[SM_MR + row];
            float mnew = fmaxf(mold, lm);
            float e0 = fast_exp(x0.x - mnew), e1 = fast_exp(x0.y - mnew);
            float e2 = fast_exp(x0.z - mnew), e3 = fast_exp(x0.w - mnew);
            float e4 = fast_exp(x1.x - mnew), e5 = fast_exp(x1.y - mnew);
            float e6 = fast_exp(x1.z - mnew), e7 = fast_exp(x1.w - mnew);
            float lsum = ((e0 + e1) + (e2 + e3)) + ((e4 + e5) + (e6 + e7));
            lsum += __shfl_xor_sync(0xffffffffu, lsum, 1);
            lsum += __shfl_xor_sync(0xffffffffu, lsum, 2);
            // split P into hi/lo
            float4 h0, h1, l0, l1;
            h0.x = __uint_as_float(f2tf32(e0)); l0.x = __uint_as_float(f2tf32(e0 - h0.x));
            h0.y = __uint_as_float(f2tf32(e1)); l0.y = __uint_as_float(f2tf32(e1 - h0.y));
            h0.z = __uint_as_float(f2tf32(e2)); l0.z = __uint_as_float(f2tf32(e2 - h0.z));
            h0.w = __uint_as_float(f2tf32(e3)); l0.w = __uint_as_float(f2tf32(e3 - h0.w));
            h1.x = __uint_as_float(f2tf32(e4)); l1.x = __uint_as_float(f2tf32(e4 - h1.x));
            h1.y = __uint_as_float(f2tf32(e5)); l1.y = __uint_as_float(f2tf32(e5 - h1.y));
            h1.z = __uint_as_float(f2tf32(e6)); l1.z = __uint_as_float(f2tf32(e6 - h1.z));
            h1.w = __uint_as_float(f2tf32(e7)); l1.w = __uint_as_float(f2tf32(e7 - h1.w));
            *(float4*)(prow)     = h0;
            *(float4*)(prow + 4) = h1;
            float* lrow_p = sm + SM_PLO + row * PSTRF + part * 8;
            *(float4*)(lrow_p)     = l0;
            *(float4*)(lrow_p + 4) = l1;
            if (part == 0) {
                float alpha = fast_exp(mold - mnew);
                sm[SM_AR + row] = alpha;
                sm[SM_LR + row] = sm[SM_LR + row] * alpha + lsum;
                sm[SM_MR + row] = mnew;
            }
        }
        __syncthreads();

        // ---- O = O*alpha + P V (3xTF32) ----
        {
            const float a0 = sm[SM_AR + wm + r];
            const float a1 = sm[SM_AR + wm + r + 8];
#pragma unroll
            for (int j = 0; j < 8; j++) {
                O[j][0] *= a0; O[j][1] *= a0;
                O[j][2] *= a1; O[j][3] *= a1;
            }
        }
#pragma unroll
        for (int ks = 0; ks < 4; ks++) {
            const int kb = ks * 8;
            const float* ph = sm + SM_PHI + (wm + r) * PSTRF + kb + t;
            const float* pl = sm + SM_PLO + (wm + r) * PSTRF + kb + t;
            uint32_t ah0 = __float_as_uint(ph[0]);
            uint32_t ah1 = __float_as_uint(ph[8 * PSTRF]);
            uint32_t ah2 = __float_as_uint(ph[4]);
            uint32_t ah3 = __float_as_uint(ph[8 * PSTRF + 4]);
            uint32_t al0 = __float_as_uint(pl[0]);
            uint32_t al1 = __float_as_uint(pl[8 * PSTRF]);
            uint32_t al2 = __float_as_uint(pl[4]);
            uint32_t al3 = __float_as_uint(pl[8 * PSTRF + 4]);
            const float* vh = Vhi + (kb + t) * KSTRF + wn_o + r;
            const float* vl = Vlo + (kb + t) * KSTRF + wn_o + r;
#pragma unroll
            for (int j = 0; j < 8; j++) {
                uint32_t bh0 = __float_as_uint(vh[8 * j]);
                uint32_t bh1 = __float_as_uint(vh[8 * j + 4 * KSTRF]);
                uint32_t bl0 = __float_as_uint(vl[8 * j]);
                uint32_t bl1 = __float_as_uint(vl[8 * j + 4 * KSTRF]);
                mma_tf32(O[j][0], O[j][1], O[j][2], O[j][3],
                         ah0, ah1, ah2, ah3, bh0, bh1);
                mma_tf32(O[j][0], O[j][1], O[j][2], O[j][3],
                         al0, al1, al2, al3, bh0, bh1);
                mma_tf32(O[j][0], O[j][1], O[j][2], O[j][3],
                         ah0, ah1, ah2, ah3, bl0, bl1);
            }
        }
    }

    // epilogue: normalize, write ctx[b, s, h*128 + d]
    {
        const int b = bh >> 4;
        const int h = bh & 15;
        const float inv0 = 1.0f / sm[SM_LR + wm + r];
        const float inv1 = 1.0f / sm[SM_LR + wm + r + 8];
        const int gs0 = q0 + wm + r;
        float* d0 = ctx + (size_t)(b * S_ + gs0) * D_ + h * HD_ + wn_o + 2 * t;
        float* d1 = ctx + (size_t)(b * S_ + gs0 + 8) * D_ + h * HD_ + wn_o + 2 * t;
#pragma unroll
        for (int j = 0; j < 8; j++) {
            float2 u0, u1;
            u0.x = O[j][0] * inv0; u0.y = O[j][1] * inv0;
            u1.x = O[j][2] * inv1; u1.y = O[j][3] * inv1;
            *(float2*)(d0 + 8 * j) = u0;
            *(float2*)(d1 + 8 * j) = u1;
        }
    }
}

// ---------------------------------------------------------------------------
// kernel_launch: x, W_qkv, b_qkv, W_out, b_out
// ---------------------------------------------------------------------------
extern "C" void kernel_launch(void* const* d_in, const int* in_sizes, int n_in,
                              void* d_out, int out_size)
{
    const float* x     = (const float*)d_in[0];
    const float* W_qkv = (const float*)d_in[1];
    const float* b_qkv = (const float*)d_in[2];
    const float* W_out = (const float*)d_in[3];
    const float* b_out = (const float*)d_in[4];
    float* out = (float*)d_out;

    float *qkv = nullptr, *ctx = nullptr;
    cudaGetSymbolAddress((void**)&qkv, g_qkv);
    cudaGetSymbolAddress((void**)&ctx, g_ctx);

    cudaFuncSetAttribute(tf32_gemm_nt_bias,
                         cudaFuncAttributeMaxDynamicSharedMemorySize, GEMM_SMEM);
    cudaFuncSetAttribute(flash_kernel,
                         cudaFuncAttributeMaxDynamicSharedMemorySize, FLASH_SMEM);

    dim3 blk(256);
    // 1) QKV projection
    tf32_gemm_nt_bias<<<dim3(QKVN / 128, M_ / 128), blk, GEMM_SMEM>>>(
        x, W_qkv, b_qkv, qkv, M_, QKVN, D_);
    // 2) RoPE in-place
    rope_kernel<<<(B_ * S_ * H_ * 16) / 256, 256>>>(qkv);
    // 3) split/transpose into tf32 hi/lo planes
    split_qkv_kernel<<<(B_ * S_ * H_ * 32) / 256, 256>>>(qkv);
    // 4) causal flash attention (3xTF32)
    flash_kernel<<<dim3(S_ / 64, B_ * H_), blk, FLASH_SMEM>>>(ctx);
    // 5) output projection
    tf32_gemm_nt_bias<<<dim3(D_ / 128, M_ / 128), blk, GEMM_SMEM>>>(
        ctx, W_out, b_out, out, M_, D_, D_);
}